// round 2
// baseline (speedup 1.0000x reference)
#include <cuda_runtime.h>
#include <math.h>

#define SEQ 32768
#define HID 1024
#define ROWS_PER_BLOCK 8

// Scratch for energies (no device allocation allowed)
__device__ float g_energies[SEQ];

// ---------------------------------------------------------------------------
// Kernel 1: energies[row] = dot(encoder_outputs[row, :], hidden)
// One warp per row, float4 vectorized, hidden staged in shared memory.
// ---------------------------------------------------------------------------
__global__ __launch_bounds__(256) void matvec_kernel(
    const float* __restrict__ hidden,
    const float* __restrict__ enc)
{
    __shared__ float4 sh_h[HID / 4];  // 4 KB

    int tid = threadIdx.x;            // 256 threads = 256 float4 of hidden
    sh_h[tid] = reinterpret_cast<const float4*>(hidden)[tid];
    __syncthreads();

    int warp = tid >> 5;
    int lane = tid & 31;
    int row  = blockIdx.x * ROWS_PER_BLOCK + warp;

    const float4* e4 = reinterpret_cast<const float4*>(enc)
                     + (size_t)row * (HID / 4);

    float acc = 0.0f;
#pragma unroll
    for (int i = 0; i < 8; i++) {
        float4 a = e4[i * 32 + lane];     // consecutive lanes -> consecutive 16B
        float4 h = sh_h[i * 32 + lane];
        acc = fmaf(a.x, h.x, acc);
        acc = fmaf(a.y, h.y, acc);
        acc = fmaf(a.z, h.z, acc);
        acc = fmaf(a.w, h.w, acc);
    }

#pragma unroll
    for (int o = 16; o; o >>= 1)
        acc += __shfl_xor_sync(0xffffffffu, acc, o);

    if (lane == 0)
        g_energies[row] = acc;
}

// ---------------------------------------------------------------------------
// Kernel 2: out = softmax(energies), single block of 1024 threads,
// 32 values per thread held in registers.
// ---------------------------------------------------------------------------
__global__ __launch_bounds__(1024) void softmax_kernel(float* __restrict__ out)
{
    __shared__ float red[32];

    int tid  = threadIdx.x;           // 0..1023
    int lane = tid & 31;
    int warp = tid >> 5;              // 0..31

    float vals[32];
    float m = -INFINITY;
#pragma unroll
    for (int i = 0; i < 32; i++) {
        vals[i] = g_energies[i * 1024 + tid];
        m = fmaxf(m, vals[i]);
    }

    // block-reduce max
#pragma unroll
    for (int o = 16; o; o >>= 1)
        m = fmaxf(m, __shfl_xor_sync(0xffffffffu, m, o));
    if (lane == 0) red[warp] = m;
    __syncthreads();
    if (warp == 0) {
        float v = red[lane];
#pragma unroll
        for (int o = 16; o; o >>= 1)
            v = fmaxf(v, __shfl_xor_sync(0xffffffffu, v, o));
        if (lane == 0) red[0] = v;
    }
    __syncthreads();
    m = red[0];
    __syncthreads();   // protect red[] reuse below

    // exp + sum
    float s = 0.0f;
#pragma unroll
    for (int i = 0; i < 32; i++) {
        vals[i] = __expf(vals[i] - m);
        s += vals[i];
    }
#pragma unroll
    for (int o = 16; o; o >>= 1)
        s += __shfl_xor_sync(0xffffffffu, s, o);
    if (lane == 0) red[warp] = s;
    __syncthreads();
    if (warp == 0) {
        float v = red[lane];
#pragma unroll
        for (int o = 16; o; o >>= 1)
            v += __shfl_xor_sync(0xffffffffu, v, o);
        if (lane == 0) red[0] = v;
    }
    __syncthreads();
    float inv = 1.0f / red[0];

#pragma unroll
    for (int i = 0; i < 32; i++)
        out[i * 1024 + tid] = vals[i] * inv;
}

// ---------------------------------------------------------------------------
extern "C" void kernel_launch(void* const* d_in, const int* in_sizes, int n_in,
                              void* d_out, int out_size)
{
    const float* hidden = (const float*)d_in[0];   // [1024]
    const float* enc    = (const float*)d_in[1];   // [32768, 1024]
    float* out          = (float*)d_out;           // [1,1,32768]

    matvec_kernel<<<SEQ / ROWS_PER_BLOCK, 256>>>(hidden, enc);
    softmax_kernel<<<1, 1024>>>(out);
}

// round 3
// speedup vs baseline: 1.0229x; 1.0229x over previous
#include <cuda_runtime.h>
#include <math.h>

#define SEQ 32768
#define HID 1024
#define ROWS_PER_BLOCK 8

// Scratch for energies (no device allocation allowed)
__device__ float g_energies[SEQ];

// ---------------------------------------------------------------------------
// Kernel 1: energies[row] = dot(encoder_outputs[row, :], hidden)
// One warp per row, float4 vectorized, hidden staged in shared memory.
// ---------------------------------------------------------------------------
__global__ __launch_bounds__(256) void matvec_kernel(
    const float* __restrict__ hidden,
    const float* __restrict__ enc)
{
    __shared__ float4 sh_h[HID / 4];  // 4 KB

    int tid = threadIdx.x;            // 256 threads = 256 float4 of hidden
    sh_h[tid] = reinterpret_cast<const float4*>(hidden)[tid];
    __syncthreads();

    int warp = tid >> 5;
    int lane = tid & 31;
    int row  = blockIdx.x * ROWS_PER_BLOCK + warp;

    const float4* e4 = reinterpret_cast<const float4*>(enc)
                     + (size_t)row * (HID / 4);

    float acc = 0.0f;
#pragma unroll
    for (int i = 0; i < 8; i++) {
        float4 a = e4[i * 32 + lane];     // consecutive lanes -> consecutive 16B
        float4 h = sh_h[i * 32 + lane];
        acc = fmaf(a.x, h.x, acc);
        acc = fmaf(a.y, h.y, acc);
        acc = fmaf(a.z, h.z, acc);
        acc = fmaf(a.w, h.w, acc);
    }

#pragma unroll
    for (int o = 16; o; o >>= 1)
        acc += __shfl_xor_sync(0xffffffffu, acc, o);

    if (lane == 0)
        g_energies[row] = acc;
}

// ---------------------------------------------------------------------------
// Kernel 2: out = softmax(energies), single block of 1024 threads,
// 32 values per thread held in registers.
// ---------------------------------------------------------------------------
__global__ __launch_bounds__(1024) void softmax_kernel(float* __restrict__ out)
{
    __shared__ float red[32];

    int tid  = threadIdx.x;           // 0..1023
    int lane = tid & 31;
    int warp = tid >> 5;              // 0..31

    float vals[32];
    float m = -INFINITY;
#pragma unroll
    for (int i = 0; i < 32; i++) {
        vals[i] = g_energies[i * 1024 + tid];
        m = fmaxf(m, vals[i]);
    }

    // block-reduce max
#pragma unroll
    for (int o = 16; o; o >>= 1)
        m = fmaxf(m, __shfl_xor_sync(0xffffffffu, m, o));
    if (lane == 0) red[warp] = m;
    __syncthreads();
    if (warp == 0) {
        float v = red[lane];
#pragma unroll
        for (int o = 16; o; o >>= 1)
            v = fmaxf(v, __shfl_xor_sync(0xffffffffu, v, o));
        if (lane == 0) red[0] = v;
    }
    __syncthreads();
    m = red[0];
    __syncthreads();   // protect red[] reuse below

    // exp + sum
    float s = 0.0f;
#pragma unroll
    for (int i = 0; i < 32; i++) {
        vals[i] = __expf(vals[i] - m);
        s += vals[i];
    }
#pragma unroll
    for (int o = 16; o; o >>= 1)
        s += __shfl_xor_sync(0xffffffffu, s, o);
    if (lane == 0) red[warp] = s;
    __syncthreads();
    if (warp == 0) {
        float v = red[lane];
#pragma unroll
        for (int o = 16; o; o >>= 1)
            v += __shfl_xor_sync(0xffffffffu, v, o);
        if (lane == 0) red[0] = v;
    }
    __syncthreads();
    float inv = 1.0f / red[0];

#pragma unroll
    for (int i = 0; i < 32; i++)
        out[i * 1024 + tid] = vals[i] * inv;
}

// ---------------------------------------------------------------------------
extern "C" void kernel_launch(void* const* d_in, const int* in_sizes, int n_in,
                              void* d_out, int out_size)
{
    const float* hidden = (const float*)d_in[0];   // [1024]
    const float* enc    = (const float*)d_in[1];   // [32768, 1024]
    float* out          = (float*)d_out;           // [1,1,32768]

    matvec_kernel<<<SEQ / ROWS_PER_BLOCK, 256>>>(hidden, enc);
    softmax_kernel<<<1, 1024>>>(out);
}